// round 10
// baseline (speedup 1.0000x reference)
#include <cuda_runtime.h>
#include <cuda_bf16.h>
#include <cstdint>

// Problem constants
#define BB 2048   // batch
#define BP 2058   // padded batch (147 CTAs * 14 rows)
#define TT 64     // timesteps
#define HH 64     // LSTM hidden
#define GG 256    // 4*H gates
#define NL 8      // LSTM layers
#define BT 14     // batch rows per CTA
#define NCTA 147

// Ping-pong inter-layer buffers, layout [T, BP, 64] (layer0 x: cols 0-15, rest zero)
__device__ float g_bufA[(size_t)TT * BP * HH + 256];
__device__ float g_bufB[(size_t)TT * BP * HH + 256];

__device__ __forceinline__ float* bufptr(int s) { return s ? g_bufB : g_bufA; }

__device__ __forceinline__ float sigm(float x) {
    return __fdividef(1.0f, 1.0f + __expf(-x));
}
__device__ __forceinline__ float tanh_(float x) {
    return __fdividef(2.0f, 1.0f + __expf(-2.0f * x)) - 1.0f;
}

// ---- packed f32x2 helpers (Blackwell FFMA2; PTX-only) ----
__device__ __forceinline__ void ffma2(uint64_t& d, uint64_t a, uint64_t b) {
    asm("fma.rn.f32x2 %0, %1, %2, %0;" : "+l"(d) : "l"(a), "l"(b));
}
__device__ __forceinline__ uint64_t pack2(float lo, float hi) {
    uint64_t r;
    asm("mov.b64 %0, {%1, %2};" : "=l"(r) : "f"(lo), "f"(hi));
    return r;
}
__device__ __forceinline__ float hsum2(uint64_t v) {
    float lo, hi;
    asm("mov.b64 {%0, %1}, %2;" : "=f"(lo), "=f"(hi) : "l"(v));
    return lo + hi;
}

// ---------------------------------------------------------------------------
// Input MLP: x[B,T,2] -> relu(x@w1^T+b1)@w2^T+b2 -> g_bufA[T,BP,64] (cols 0-15)
// ---------------------------------------------------------------------------
__global__ void mlp_in_kernel(const float* __restrict__ x,
                              const float* __restrict__ w1, const float* __restrict__ b1,
                              const float* __restrict__ w2, const float* __restrict__ b2)
{
    __shared__ float s_w1[16][2], s_b1[16], s_w2[16][16], s_b2[16];
    int tid = threadIdx.x;
    if (tid < 32) { s_w1[tid / 2][tid % 2] = w1[tid]; }
    if (tid < 16) { s_b1[tid] = b1[tid]; s_b2[tid] = b2[tid]; }
    if (tid >= 32 && tid < 32 + 256) {
        int i = tid - 32;
        s_w2[i / 16][i % 16] = w2[i];
    }
    __syncthreads();

    int idx = blockIdx.x * blockDim.x + tid;      // idx = b*T + t
    int b = idx / TT;
    int t = idx % TT;
    float x0 = x[(size_t)idx * 2 + 0];
    float x1 = x[(size_t)idx * 2 + 1];

    float h1[16];
#pragma unroll
    for (int j = 0; j < 16; j++) {
        float v = fmaf(s_w1[j][0], x0, fmaf(s_w1[j][1], x1, s_b1[j]));
        h1[j] = fmaxf(v, 0.0f);
    }
    float* dst = g_bufA + ((size_t)t * BP + b) * 64;
#pragma unroll
    for (int j = 0; j < 16; j++) {
        float o = s_b2[j];
#pragma unroll
        for (int k = 0; k < 16; k++) o = fmaf(s_w2[j][k], h1[k], o);
        dst[j] = o;
    }
#pragma unroll
    for (int j = 16; j < 64; j++) dst[j] = 0.0f;
}

// ---------------------------------------------------------------------------
// Fused LSTM layer, fine-grained 4-quarter pipeline.
// 512 threads = 128 col-pairs (jA=p, jB=p+128) x 4 K-splits.
// K = concat(x[64], h[64]); q=0,1 own x ks [q*32,+32); q=2,3 own h ks.
// Weights: 2 cols x 32 ks = 32 u64 regs. Step schedule:
//   ML(Q0) |bar| ML(Q1)+EW(Q0) |bar| ML(Q2)+EW(Q1) |bar| ML(Q3)+EW(Q2)
//   |bar| EW(Q3)+x(t+1)-commit |bar     (Q0..Q2 = 4 rows, Q3 = 2 rows)
// EW is spread across ALL 16 warps (predicated lanes) for barrier balance.
// Partials in s_gp[plane=gate*4+q][BT][64].
// ---------------------------------------------------------------------------
template <int IR>
__global__ void __launch_bounds__(512, 1)
lstm_fused(int insel, int outsel,
           const float* __restrict__ w_ih, const float* __restrict__ w_hh,
           const float* __restrict__ b_ih, const float* __restrict__ b_hh)
{
    extern __shared__ float smem[];
    float* s_x  = smem;                 // [2][BT][64]
    float* s_h  = s_x + 2 * BT * 64;    // [BT][64]
    float* s_c  = s_h + BT * 64;        // [BT][64]
    float* s_gp = s_c + BT * 64;        // [16][BT][64]  plane = gate*4+q

    const float* in  = bufptr(insel);
    float*       out = bufptr(outsel);
    const int tid  = threadIdx.x;
    const int lane = tid & 31;
    const int wid  = tid >> 5;
    const int p    = tid & 127;         // column pair
    const int q    = tid >> 7;          // K split 0..3
    const int b0   = blockIdx.x * BT;
    const int glo  = p >> 6;            // gate of jA: 0=i, 1=f
    const int u    = p & 63;            // unit

    // weights: c=0 -> col jA=p (gate glo), c=1 -> col jB=p+128 (gate 2+glo)
    uint64_t w[2][16];
#pragma unroll
    for (int c = 0; c < 2; c++) {
        const int j = p + c * 128;
#pragma unroll
        for (int kk = 0; kk < 32; kk += 2) {
            float a, b;
            if (q < 2) {
                int k = q * 32 + kk;
                a = (k     < IR) ? w_ih[(size_t)j * IR + k]     : 0.0f;
                b = (k + 1 < IR) ? w_ih[(size_t)j * IR + k + 1] : 0.0f;
            } else {
                int k = (q - 2) * 32 + kk;
                a = w_hh[(size_t)j * 64 + k];
                b = w_hh[(size_t)j * 64 + k + 1];
            }
            w[c][kk / 2] = pack2(a, b);
        }
    }
    uint64_t bias[2];
#pragma unroll
    for (int c = 0; c < 2; c++) {
        const int j = p + c * 128;
        bias[c] = (q == 0) ? pack2(b_ih[j] + b_hh[j], 0.0f) : 0ull;
    }

    // h0 = c0 = 0; stage x(0)
    for (int i = tid; i < BT * 64; i += 512) { s_h[i] = 0.0f; s_c[i] = 0.0f; }
    if (tid < BT * 16)
        ((float4*)s_x)[tid] = ((const float4*)(in + (size_t)b0 * 64))[tid];
    __syncthreads();

    for (int t = 0; t < TT; t++) {
        const int cur = t & 1, nxt = cur ^ 1;
        const float* ap = (q < 2) ? (s_x + cur * BT * 64 + q * 32)
                                  : (s_h + (q - 2) * 32);

        // prefetch x(t+1) into regs (hidden under mainloop)
        float4 pf;
        const bool do_pf = (t + 1 < TT) && (tid < BT * 16);
        if (do_pf)
            pf = ((const float4*)(in + ((size_t)(t + 1) * BP + b0) * 64))[tid];

        // ---- ML quarter: rows [rs, rs+rn), rn <= 4 ----
        auto ml_rows = [&](int rs, int rn) {
            uint64_t accA[4], accB[4];
#pragma unroll
            for (int r = 0; r < 4; r++) { accA[r] = bias[0]; accB[r] = bias[1]; }
#pragma unroll
            for (int kk = 0; kk < 32; kk += 4) {
#pragma unroll
                for (int r = 0; r < 4; r++) {
                    if (r < rn) {
                        ulonglong2 v = *(const ulonglong2*)(ap + (size_t)(rs + r) * 64 + kk);
                        ffma2(accA[r], v.x, w[0][kk / 2]);
                        ffma2(accA[r], v.y, w[0][kk / 2 + 1]);
                        ffma2(accB[r], v.x, w[1][kk / 2]);
                        ffma2(accB[r], v.y, w[1][kk / 2 + 1]);
                    }
                }
            }
#pragma unroll
            for (int r = 0; r < 4; r++) {
                if (r < rn) {
                    s_gp[(size_t)((glo)     * 4 + q) * BT * 64 + (rs + r) * 64 + u] = hsum2(accA[r]);
                    s_gp[(size_t)((2 + glo) * 4 + q) * BT * 64 + (rs + r) * 64 + u] = hsum2(accB[r]);
                }
            }
        };

        // ---- EW quarter: rows [rs, rs+rn); spread over all 16 warps ----
        auto ew_rows = [&](int rs, int rn) {
            const int nunits = rn * 64;            // 256 or 128
            const int per    = nunits / 16;        // units per warp: 16 or 8
            const int sh     = 32 / per;           // lane stride: 2 or 4
            const int sub    = (sh == 2) ? (lane >> 1) : (lane >> 2);
            const bool act   = (lane & (sh - 1)) == 0;
            if (act) {
                const int unit = wid * per + sub;  // 0..nunits-1
                const int r  = rs + (unit >> 6);
                const int uu = unit & 63;
                float gi = 0.f, gf = 0.f, gg = 0.f, go = 0.f;
#pragma unroll
                for (int qq = 0; qq < 4; qq++) {
                    const float* gpb = s_gp + (size_t)qq * BT * 64 + r * 64 + uu;
                    gi += gpb[0 * 4 * BT * 64];
                    gf += gpb[1 * 4 * BT * 64];
                    gg += gpb[2 * 4 * BT * 64];
                    go += gpb[3 * 4 * BT * 64];
                }
                float iv = sigm(gi), fv = sigm(gf), gv = tanh_(gg), ov = sigm(go);
                float cc = fmaf(fv, s_c[r * 64 + uu], iv * gv);
                float hh = ov * tanh_(cc);
                s_c[r * 64 + uu] = cc;
                s_h[r * 64 + uu] = hh;
                out[((size_t)t * BP + b0 + r) * 64 + uu] = hh;
            }
        };

        ml_rows(0, 4);
        __syncthreads();                 // Q0 partials ready
        ml_rows(4, 4);  ew_rows(0, 4);
        __syncthreads();                 // Q1 partials ready; h rows 0-3 final
        ml_rows(8, 4);  ew_rows(4, 4);
        __syncthreads();                 // Q2 partials ready; h rows 4-7 final
        ml_rows(12, 2); ew_rows(8, 4);
        __syncthreads();                 // Q3 partials ready; h rows 8-11 final
        ew_rows(12, 2);
        if (do_pf)
            ((float4*)(s_x + nxt * BT * 64))[tid] = pf;
        __syncthreads();                 // h complete, x(t+1) staged
    }
}

// ---------------------------------------------------------------------------
// Output MLP: h[T,BP,64] -> relu(h@wo1^T+bo1)@wo2^T+bo2 -> out[B,T,4]
// ---------------------------------------------------------------------------
__global__ void mlp_out_kernel(int insel,
                               const float* __restrict__ wo1, const float* __restrict__ bo1,
                               const float* __restrict__ wo2, const float* __restrict__ bo2,
                               float* __restrict__ outp)
{
    __shared__ float s_w1[32][64];
    __shared__ float s_b1[32];
    __shared__ float s_w2[4][32];
    __shared__ float s_b2[4];
    int tid = threadIdx.x;
    for (int i = tid; i < 32 * 64; i += 256) s_w1[i / 64][i % 64] = wo1[i];
    if (tid < 32) s_b1[tid] = bo1[tid];
    if (tid < 128) s_w2[tid / 32][tid % 32] = wo2[tid];
    if (tid < 4) s_b2[tid] = bo2[tid];
    __syncthreads();

    const float* in = bufptr(insel);
    int idx = blockIdx.x * blockDim.x + tid;   // idx = t*B + b (coalesced h reads)
    int t = idx / BB;
    int b = idx % BB;

    float h[64];
    const float4* src = reinterpret_cast<const float4*>(in + ((size_t)t * BP + b) * 64);
#pragma unroll
    for (int i = 0; i < 16; i++) {
        float4 v = src[i];
        h[4 * i + 0] = v.x; h[4 * i + 1] = v.y; h[4 * i + 2] = v.z; h[4 * i + 3] = v.w;
    }

    float h2[32];
#pragma unroll
    for (int j = 0; j < 32; j++) {
        float o = s_b1[j];
#pragma unroll
        for (int k = 0; k < 64; k++) o = fmaf(s_w1[j][k], h[k], o);
        h2[j] = fmaxf(o, 0.0f);
    }
    float* dst = outp + ((size_t)b * TT + t) * 4;
#pragma unroll
    for (int j = 0; j < 4; j++) {
        float o = s_b2[j];
#pragma unroll
        for (int k = 0; k < 32; k++) o = fmaf(s_w2[j][k], h2[k], o);
        dst[j] = o;
    }
}

// ---------------------------------------------------------------------------
extern "C" void kernel_launch(void* const* d_in, const int* in_sizes, int n_in,
                              void* d_out, int out_size)
{
    const float* x     = (const float*)d_in[0];
    const float* w1    = (const float*)d_in[1];
    const float* b1    = (const float*)d_in[2];
    const float* w2    = (const float*)d_in[3];
    const float* b2    = (const float*)d_in[4];
    const float* w_ih0 = (const float*)d_in[5];
    const float* w_hh0 = (const float*)d_in[6];
    const float* b_ih0 = (const float*)d_in[7];
    const float* b_hh0 = (const float*)d_in[8];
    const float* w_ih  = (const float*)d_in[9];   // (7, 256, 64)
    const float* w_hh  = (const float*)d_in[10];  // (7, 256, 64)
    const float* b_ih  = (const float*)d_in[11];  // (7, 256)
    const float* b_hh  = (const float*)d_in[12];  // (7, 256)
    const float* wo1   = (const float*)d_in[13];
    const float* bo1   = (const float*)d_in[14];
    const float* wo2   = (const float*)d_in[15];
    const float* bo2   = (const float*)d_in[16];
    float* outp = (float*)d_out;

    const int smem_sz = (2 * BT * 64 + 2 * BT * 64 + 16 * BT * 64) * 4;  // 71680 B
    cudaFuncSetAttribute(lstm_fused<16>, cudaFuncAttributeMaxDynamicSharedMemorySize, smem_sz);
    cudaFuncSetAttribute(lstm_fused<64>, cudaFuncAttributeMaxDynamicSharedMemorySize, smem_sz);

    const int nelem = BB * TT;               // 131072

    mlp_in_kernel<<<nelem / 256, 256>>>(x, w1, b1, w2, b2);

    // layer 0: A -> B (x cols 16-63 are zero; IR=16 weights)
    lstm_fused<16><<<NCTA, 512, smem_sz>>>(0, 1, w_ih0, w_hh0, b_ih0, b_hh0);

    // layers 1..7: ping-pong B->A->B->...
    int cur = 1;
    for (int l = 0; l < NL - 1; l++) {
        int nxt = cur ^ 1;
        lstm_fused<64><<<NCTA, 512, smem_sz>>>(cur, nxt,
                                               w_ih + (size_t)l * GG * HH,
                                               w_hh + (size_t)l * GG * HH,
                                               b_ih + (size_t)l * GG,
                                               b_hh + (size_t)l * GG);
        cur = nxt;
    }

    mlp_out_kernel<<<nelem / 256, 256>>>(cur, wo1, bo1, wo2, bo2, outp);
}

// round 11
// speedup vs baseline: 1.0981x; 1.0981x over previous
#include <cuda_runtime.h>
#include <cuda_bf16.h>
#include <cstdint>

// Problem constants
#define BB 2048   // batch
#define BP 2058   // padded batch (147 CTAs * 14 rows)
#define TT 64     // timesteps
#define HH 64     // LSTM hidden
#define GG 256    // 4*H gates
#define NL 8      // LSTM layers
#define BT 14     // batch rows per CTA
#define NCTA 147

// Ping-pong inter-layer buffers, layout [T, BP, 64] (layer0 x: cols 0-15, rest zero)
__device__ float g_bufA[(size_t)TT * BP * HH + 256];
__device__ float g_bufB[(size_t)TT * BP * HH + 256];

__device__ __forceinline__ float* bufptr(int s) { return s ? g_bufB : g_bufA; }

__device__ __forceinline__ float sigm(float x) {
    return __fdividef(1.0f, 1.0f + __expf(-x));
}
__device__ __forceinline__ float tanh_(float x) {
    return __fdividef(2.0f, 1.0f + __expf(-2.0f * x)) - 1.0f;
}

// ---- packed f32x2 helpers (Blackwell FFMA2; PTX-only) ----
__device__ __forceinline__ void ffma2(uint64_t& d, uint64_t a, uint64_t b) {
    asm("fma.rn.f32x2 %0, %1, %2, %0;" : "+l"(d) : "l"(a), "l"(b));
}
__device__ __forceinline__ uint64_t pack2(float lo, float hi) {
    uint64_t r;
    asm("mov.b64 %0, {%1, %2};" : "=l"(r) : "f"(lo), "f"(hi));
    return r;
}
__device__ __forceinline__ float hsum2(uint64_t v) {
    float lo, hi;
    asm("mov.b64 {%0, %1}, %2;" : "=f"(lo), "=f"(hi) : "l"(v));
    return lo + hi;
}

// ---------------------------------------------------------------------------
// Input MLP: x[B,T,2] -> relu(x@w1^T+b1)@w2^T+b2 -> g_bufA[T,BP,64] (cols 0-15)
// ---------------------------------------------------------------------------
__global__ void mlp_in_kernel(const float* __restrict__ x,
                              const float* __restrict__ w1, const float* __restrict__ b1,
                              const float* __restrict__ w2, const float* __restrict__ b2)
{
    __shared__ float s_w1[16][2], s_b1[16], s_w2[16][16], s_b2[16];
    int tid = threadIdx.x;
    if (tid < 32) { s_w1[tid / 2][tid % 2] = w1[tid]; }
    if (tid < 16) { s_b1[tid] = b1[tid]; s_b2[tid] = b2[tid]; }
    if (tid >= 32 && tid < 32 + 256) {
        int i = tid - 32;
        s_w2[i / 16][i % 16] = w2[i];
    }
    __syncthreads();

    int idx = blockIdx.x * blockDim.x + tid;      // idx = b*T + t
    int b = idx / TT;
    int t = idx % TT;
    float x0 = x[(size_t)idx * 2 + 0];
    float x1 = x[(size_t)idx * 2 + 1];

    float h1[16];
#pragma unroll
    for (int j = 0; j < 16; j++) {
        float v = fmaf(s_w1[j][0], x0, fmaf(s_w1[j][1], x1, s_b1[j]));
        h1[j] = fmaxf(v, 0.0f);
    }
    float* dst = g_bufA + ((size_t)t * BP + b) * 64;
#pragma unroll
    for (int j = 0; j < 16; j++) {
        float o = s_b2[j];
#pragma unroll
        for (int k = 0; k < 16; k++) o = fmaf(s_w2[j][k], h1[k], o);
        dst[j] = o;
    }
#pragma unroll
    for (int j = 16; j < 64; j++) dst[j] = 0.0f;
}

// ---------------------------------------------------------------------------
// Fused LSTM layer, x-part-ahead 2-phase pipeline.
// 512 threads = 128 col-pairs (jA=p, jB=p+128) x 4 K-splits (16 ks each half).
// gp[2][16 planes][BT][64]: plane = gate*4+q. Step t:
//   Phase A: gp[t&1] (x-partials of t, incl. bias) += h(t)-part   (in place)
//   bar
//   Phase B: ML x(t+1)-part -> gp[(t+1)&1]  ||  EW(t) from gp[t&1]
//            || commit staged x(t+2)
//   bar
// Both phases are ~1792-cyc fma-saturated; EW hides under phase B's ML.
// ---------------------------------------------------------------------------
template <int IR>
__global__ void __launch_bounds__(512, 1)
lstm_fused(int insel, int outsel,
           const float* __restrict__ w_ih, const float* __restrict__ w_hh,
           const float* __restrict__ b_ih, const float* __restrict__ b_hh)
{
    extern __shared__ float smem[];
    float* s_x  = smem;                 // [2][BT][64]
    float* s_h  = s_x + 2 * BT * 64;    // [BT][64]
    float* s_c  = s_h + BT * 64;        // [BT][64]
    float* s_gp = s_c + BT * 64;        // [2][16][BT][64]

    const float* in  = bufptr(insel);
    float*       out = bufptr(outsel);
    const int tid = threadIdx.x;
    const int p   = tid & 127;          // column pair
    const int q   = tid >> 7;           // K split 0..3 (16-k windows)
    const int b0  = blockIdx.x * BT;
    const int glo = p >> 6;             // gate of jA: 0=i, 1=f
    const int u   = p & 63;             // unit
    const int plA = glo * 4 + q;        // plane of col jA
    const int plB = (2 + glo) * 4 + q;  // plane of col jB

    // weights: wX = x-part window [q*16,+16) (zero-padded past IR), wH = h-part
    uint64_t wX[2][8], wH[2][8];
#pragma unroll
    for (int c = 0; c < 2; c++) {
        const int j = p + c * 128;
#pragma unroll
        for (int kk = 0; kk < 16; kk += 2) {
            int kx = q * 16 + kk;
            float a = (kx     < IR) ? w_ih[(size_t)j * IR + kx]     : 0.0f;
            float b = (kx + 1 < IR) ? w_ih[(size_t)j * IR + kx + 1] : 0.0f;
            wX[c][kk / 2] = pack2(a, b);
            wH[c][kk / 2] = pack2(w_hh[(size_t)j * 64 + q * 16 + kk],
                                  w_hh[(size_t)j * 64 + q * 16 + kk + 1]);
        }
    }
    uint64_t bias[2];
#pragma unroll
    for (int c = 0; c < 2; c++) {
        const int j = p + c * 128;
        bias[c] = (q == 0) ? pack2(b_ih[j] + b_hh[j], 0.0f) : 0ull;
    }

    // ---- ML x-part: gates_x(xbuf) -> gp[gsel] (with bias) ----
    auto mlx = [&](const float* xb, int gsel) {
        float* gpb = s_gp + (size_t)gsel * 16 * BT * 64;
#pragma unroll
        for (int ch = 0; ch < 4; ch++) {
            const int rs = ch * 4;
            const int rn = (ch < 3) ? 4 : 2;
            uint64_t acc[2][4];
#pragma unroll
            for (int r = 0; r < 4; r++) { acc[0][r] = bias[0]; acc[1][r] = bias[1]; }
#pragma unroll
            for (int kk = 0; kk < 16; kk += 4) {
#pragma unroll
                for (int r = 0; r < 4; r++) {
                    if (r < rn) {
                        ulonglong2 v = *(const ulonglong2*)(xb + (size_t)(rs + r) * 64 + q * 16 + kk);
                        ffma2(acc[0][r], v.x, wX[0][kk / 2]);
                        ffma2(acc[0][r], v.y, wX[0][kk / 2 + 1]);
                        ffma2(acc[1][r], v.x, wX[1][kk / 2]);
                        ffma2(acc[1][r], v.y, wX[1][kk / 2 + 1]);
                    }
                }
            }
#pragma unroll
            for (int r = 0; r < 4; r++) {
                if (r < rn) {
                    gpb[(size_t)plA * BT * 64 + (rs + r) * 64 + u] = hsum2(acc[0][r]);
                    gpb[(size_t)plB * BT * 64 + (rs + r) * 64 + u] = hsum2(acc[1][r]);
                }
            }
        }
    };

    // ---- ML h-part: gp[gsel] += gates_h(s_h) (in place) ----
    auto mlh = [&](int gsel) {
        float* gpb = s_gp + (size_t)gsel * 16 * BT * 64;
#pragma unroll
        for (int ch = 0; ch < 4; ch++) {
            const int rs = ch * 4;
            const int rn = (ch < 3) ? 4 : 2;
            uint64_t acc[2][4];
#pragma unroll
            for (int r = 0; r < 4; r++) {
                if (r < rn) {
                    acc[0][r] = pack2(gpb[(size_t)plA * BT * 64 + (rs + r) * 64 + u], 0.0f);
                    acc[1][r] = pack2(gpb[(size_t)plB * BT * 64 + (rs + r) * 64 + u], 0.0f);
                }
            }
#pragma unroll
            for (int kk = 0; kk < 16; kk += 4) {
#pragma unroll
                for (int r = 0; r < 4; r++) {
                    if (r < rn) {
                        ulonglong2 v = *(const ulonglong2*)(s_h + (size_t)(rs + r) * 64 + q * 16 + kk);
                        ffma2(acc[0][r], v.x, wH[0][kk / 2]);
                        ffma2(acc[0][r], v.y, wH[0][kk / 2 + 1]);
                        ffma2(acc[1][r], v.x, wH[1][kk / 2]);
                        ffma2(acc[1][r], v.y, wH[1][kk / 2 + 1]);
                    }
                }
            }
#pragma unroll
            for (int r = 0; r < 4; r++) {
                if (r < rn) {
                    gpb[(size_t)plA * BT * 64 + (rs + r) * 64 + u] = hsum2(acc[0][r]);
                    gpb[(size_t)plB * BT * 64 + (rs + r) * 64 + u] = hsum2(acc[1][r]);
                }
            }
        }
    };

    // ---- EW: fold gp[gsel] planes, cell update, write h ----
    auto ew = [&](int gsel, int t) {
        const float* gpb = s_gp + (size_t)gsel * 16 * BT * 64;
#pragma unroll
        for (int e = 0; e < 2; e++) {
            int ul = e * 512 + tid;
            if (ul < BT * 64) {
                int r  = ul >> 6;
                int uu = ul & 63;
                float gi = 0.f, gf = 0.f, gg = 0.f, go = 0.f;
#pragma unroll
                for (int qq = 0; qq < 4; qq++) {
                    const float* b4 = gpb + (size_t)qq * BT * 64 + r * 64 + uu;
                    gi += b4[0 * 4 * BT * 64];
                    gf += b4[1 * 4 * BT * 64];
                    gg += b4[2 * 4 * BT * 64];
                    go += b4[3 * 4 * BT * 64];
                }
                float iv = sigm(gi), fv = sigm(gf), gv = tanh_(gg), ov = sigm(go);
                float cc = fmaf(fv, s_c[r * 64 + uu], iv * gv);
                float hh = ov * tanh_(cc);
                s_c[r * 64 + uu] = cc;
                s_h[r * 64 + uu] = hh;
                out[((size_t)t * BP + b0 + r) * 64 + uu] = hh;
            }
        }
    };

    // ---- prologue: h0=c0=0; stage x(0), x(1); x-partials for t=0 ----
    for (int i = tid; i < BT * 64; i += 512) { s_h[i] = 0.0f; s_c[i] = 0.0f; }
    if (tid < BT * 16)
        ((float4*)s_x)[tid] = ((const float4*)(in + (size_t)b0 * 64))[tid];
    __syncthreads();
    mlx(s_x, 0);
    if (tid < BT * 16)
        ((float4*)(s_x + BT * 64))[tid] = ((const float4*)(in + ((size_t)BP + b0) * 64))[tid];
    __syncthreads();

    for (int t = 0; t < TT; t++) {
        const int cur = t & 1, nx = cur ^ 1;

        // prefetch x(t+2) into regs (hidden under phase A)
        float4 pf;
        const bool do_pf = (t + 2 < TT) && (tid < BT * 16);
        if (do_pf)
            pf = ((const float4*)(in + ((size_t)(t + 2) * BP + b0) * 64))[tid];

        // ---- Phase A: gp[cur] += h(t)-part ----
        mlh(cur);
        __syncthreads();

        // ---- Phase B: ML x(t+1)-part -> gp[nx]  ||  EW(t)  ||  x(t+2) commit ----
        if (t + 1 < TT) mlx(s_x + nx * BT * 64, nx);
        ew(cur, t);
        if (do_pf)
            ((float4*)(s_x + cur * BT * 64))[tid] = pf;   // x(t) dead -> reuse its buffer
        __syncthreads();
    }
}

// ---------------------------------------------------------------------------
// Output MLP: h[T,BP,64] -> relu(h@wo1^T+bo1)@wo2^T+bo2 -> out[B,T,4]
// ---------------------------------------------------------------------------
__global__ void mlp_out_kernel(int insel,
                               const float* __restrict__ wo1, const float* __restrict__ bo1,
                               const float* __restrict__ wo2, const float* __restrict__ bo2,
                               float* __restrict__ outp)
{
    __shared__ float s_w1[32][64];
    __shared__ float s_b1[32];
    __shared__ float s_w2[4][32];
    __shared__ float s_b2[4];
    int tid = threadIdx.x;
    for (int i = tid; i < 32 * 64; i += 256) s_w1[i / 64][i % 64] = wo1[i];
    if (tid < 32) s_b1[tid] = bo1[tid];
    if (tid < 128) s_w2[tid / 32][tid % 32] = wo2[tid];
    if (tid < 4) s_b2[tid] = bo2[tid];
    __syncthreads();

    const float* in = bufptr(insel);
    int idx = blockIdx.x * blockDim.x + tid;   // idx = t*B + b (coalesced h reads)
    int t = idx / BB;
    int b = idx % BB;

    float h[64];
    const float4* src = reinterpret_cast<const float4*>(in + ((size_t)t * BP + b) * 64);
#pragma unroll
    for (int i = 0; i < 16; i++) {
        float4 v = src[i];
        h[4 * i + 0] = v.x; h[4 * i + 1] = v.y; h[4 * i + 2] = v.z; h[4 * i + 3] = v.w;
    }

    float h2[32];
#pragma unroll
    for (int j = 0; j < 32; j++) {
        float o = s_b1[j];
#pragma unroll
        for (int k = 0; k < 64; k++) o = fmaf(s_w1[j][k], h[k], o);
        h2[j] = fmaxf(o, 0.0f);
    }
    float* dst = outp + ((size_t)b * TT + t) * 4;
#pragma unroll
    for (int j = 0; j < 4; j++) {
        float o = s_b2[j];
#pragma unroll
        for (int k = 0; k < 32; k++) o = fmaf(s_w2[j][k], h2[k], o);
        dst[j] = o;
    }
}

// ---------------------------------------------------------------------------
extern "C" void kernel_launch(void* const* d_in, const int* in_sizes, int n_in,
                              void* d_out, int out_size)
{
    const float* x     = (const float*)d_in[0];
    const float* w1    = (const float*)d_in[1];
    const float* b1    = (const float*)d_in[2];
    const float* w2    = (const float*)d_in[3];
    const float* b2    = (const float*)d_in[4];
    const float* w_ih0 = (const float*)d_in[5];
    const float* w_hh0 = (const float*)d_in[6];
    const float* b_ih0 = (const float*)d_in[7];
    const float* b_hh0 = (const float*)d_in[8];
    const float* w_ih  = (const float*)d_in[9];   // (7, 256, 64)
    const float* w_hh  = (const float*)d_in[10];  // (7, 256, 64)
    const float* b_ih  = (const float*)d_in[11];  // (7, 256)
    const float* b_hh  = (const float*)d_in[12];  // (7, 256)
    const float* wo1   = (const float*)d_in[13];
    const float* bo1   = (const float*)d_in[14];
    const float* wo2   = (const float*)d_in[15];
    const float* bo2   = (const float*)d_in[16];
    float* outp = (float*)d_out;

    // smem: x(2) + h + c + gp(2*16) planes of BT*64 floats
    const int smem_sz = (2 + 1 + 1 + 32) * BT * 64 * 4;   // 129024 B
    cudaFuncSetAttribute(lstm_fused<16>, cudaFuncAttributeMaxDynamicSharedMemorySize, smem_sz);
    cudaFuncSetAttribute(lstm_fused<64>, cudaFuncAttributeMaxDynamicSharedMemorySize, smem_sz);

    const int nelem = BB * TT;               // 131072

    mlp_in_kernel<<<nelem / 256, 256>>>(x, w1, b1, w2, b2);

    // layer 0: A -> B (x cols 16-63 are zero; IR=16 weights)
    lstm_fused<16><<<NCTA, 512, smem_sz>>>(0, 1, w_ih0, w_hh0, b_ih0, b_hh0);

    // layers 1..7: ping-pong B->A->B->...
    int cur = 1;
    for (int l = 0; l < NL - 1; l++) {
        int nxt = cur ^ 1;
        lstm_fused<64><<<NCTA, 512, smem_sz>>>(cur, nxt,
                                               w_ih + (size_t)l * GG * HH,
                                               w_hh + (size_t)l * GG * HH,
                                               b_ih + (size_t)l * GG,
                                               b_hh + (size_t)l * GG);
        cur = nxt;
    }

    mlp_out_kernel<<<nelem / 256, 256>>>(cur, wo1, bo1, wo2, bo2, outp);
}

// round 12
// speedup vs baseline: 1.1468x; 1.0443x over previous
#include <cuda_runtime.h>
#include <cuda_bf16.h>
#include <cstdint>

// Problem constants
#define BB 2048   // batch
#define BP 2058   // padded batch (147 CTAs * 14 rows)
#define TT 64     // timesteps
#define HH 64     // LSTM hidden
#define GG 256    // 4*H gates
#define NL 8      // LSTM layers
#define BT 14     // batch rows per CTA
#define NCTA 147

#define LOG2E 1.4426950408889634f

// Ping-pong inter-layer buffers, layout [T, BP, 64] (layer0 x: cols 0-15, rest zero)
__device__ float g_bufA[(size_t)TT * BP * HH + 256];
__device__ float g_bufB[(size_t)TT * BP * HH + 256];

__device__ __forceinline__ float* bufptr(int s) { return s ? g_bufB : g_bufA; }

__device__ __forceinline__ float fast_ex2(float x) {
    float r;
    asm("ex2.approx.ftz.f32 %0, %1;" : "=f"(r) : "f"(x));
    return r;
}
// y = log2e * g  -> sigmoid(g)
__device__ __forceinline__ float sigm2(float y) {
    return __fdividef(1.0f, 1.0f + fast_ex2(-y));
}
// y = 2*log2e * g -> tanh(g)
__device__ __forceinline__ float tanh2(float y) {
    return __fdividef(2.0f, 1.0f + fast_ex2(-y)) - 1.0f;
}

// ---- packed f32x2 helpers (Blackwell FFMA2; PTX-only) ----
__device__ __forceinline__ void ffma2(uint64_t& d, uint64_t a, uint64_t b) {
    asm("fma.rn.f32x2 %0, %1, %2, %0;" : "+l"(d) : "l"(a), "l"(b));
}
__device__ __forceinline__ uint64_t pack2(float lo, float hi) {
    uint64_t r;
    asm("mov.b64 %0, {%1, %2};" : "=l"(r) : "f"(lo), "f"(hi));
    return r;
}
__device__ __forceinline__ float hsum2(uint64_t v) {
    float lo, hi;
    asm("mov.b64 {%0, %1}, %2;" : "=f"(lo), "=f"(hi) : "l"(v));
    return lo + hi;
}

// ---------------------------------------------------------------------------
// Input MLP: x[B,T,2] -> relu(x@w1^T+b1)@w2^T+b2 -> g_bufA[T,BP,64] (cols 0-15)
// ---------------------------------------------------------------------------
__global__ void mlp_in_kernel(const float* __restrict__ x,
                              const float* __restrict__ w1, const float* __restrict__ b1,
                              const float* __restrict__ w2, const float* __restrict__ b2)
{
    __shared__ float s_w1[16][2], s_b1[16], s_w2[16][16], s_b2[16];
    int tid = threadIdx.x;
    if (tid < 32) { s_w1[tid / 2][tid % 2] = w1[tid]; }
    if (tid < 16) { s_b1[tid] = b1[tid]; s_b2[tid] = b2[tid]; }
    if (tid >= 32 && tid < 32 + 256) {
        int i = tid - 32;
        s_w2[i / 16][i % 16] = w2[i];
    }
    __syncthreads();

    int idx = blockIdx.x * blockDim.x + tid;      // idx = b*T + t
    int b = idx / TT;
    int t = idx % TT;
    float x0 = x[(size_t)idx * 2 + 0];
    float x1 = x[(size_t)idx * 2 + 1];

    float h1[16];
#pragma unroll
    for (int j = 0; j < 16; j++) {
        float v = fmaf(s_w1[j][0], x0, fmaf(s_w1[j][1], x1, s_b1[j]));
        h1[j] = fmaxf(v, 0.0f);
    }
    float* dst = g_bufA + ((size_t)t * BP + b) * 64;
#pragma unroll
    for (int j = 0; j < 16; j++) {
        float o = s_b2[j];
#pragma unroll
        for (int k = 0; k < 16; k++) o = fmaf(s_w2[j][k], h1[k], o);
        dst[j] = o;
    }
#pragma unroll
    for (int j = 16; j < 64; j++) dst[j] = 0.0f;
}

// ---------------------------------------------------------------------------
// Fused LSTM layer (R8 skeleton, surgical updates).
// 512 threads = 128 col-pairs (jA=p, jB=p+128) x 4 K-splits.
// K = concat(x[64], h[64]); q=0,1 own x ks [q*32,+32); q=2,3 own h ks.
// Weights prescaled by log2e (sigmoid gates) / 2*log2e (tanh gate) so EW uses
// bare ex2.approx. Step schedule (3 barriers):
//   [ML rows0-6 + x(t+1) commit] bar [ML rows7-13 || EW rows0-6]
//   bar [EW rows7-13] bar
// Partials in s_gp[plane=gate*4+q][BT][64].
// ---------------------------------------------------------------------------
template <int IR>
__global__ void __launch_bounds__(512, 1)
lstm_fused(int insel, int outsel,
           const float* __restrict__ w_ih, const float* __restrict__ w_hh,
           const float* __restrict__ b_ih, const float* __restrict__ b_hh)
{
    extern __shared__ float smem[];
    float* s_x  = smem;                 // [2][BT][64]
    float* s_h  = s_x + 2 * BT * 64;    // [BT][64]
    float* s_c  = s_h + BT * 64;        // [BT][64]
    float* s_gp = s_c + BT * 64;        // [16][BT][64]  plane = gate*4+q

    const float* in  = bufptr(insel);
    float*       out = bufptr(outsel);
    const int tid = threadIdx.x;
    const int p   = tid & 127;          // column pair
    const int q   = tid >> 7;           // K split 0..3
    const int b0  = blockIdx.x * BT;
    const int glo = p >> 6;             // gate of jA: 0=i, 1=f
    const int u   = p & 63;             // unit

    // gate scales: jA = p (gates i/f, sigmoid) -> log2e
    //              jB = p+128 (p<64: gate g tanh -> 2log2e; p>=64: gate o -> log2e)
    const float scA = LOG2E;
    const float scB = (glo == 0) ? 2.0f * LOG2E : LOG2E;

    // weights (prescaled): c=0 -> col jA, c=1 -> col jB
    uint64_t w[2][16];
#pragma unroll
    for (int c = 0; c < 2; c++) {
        const int j = p + c * 128;
        const float sc = c ? scB : scA;
#pragma unroll
        for (int kk = 0; kk < 32; kk += 2) {
            float a, b;
            if (q < 2) {
                int k = q * 32 + kk;
                a = (k     < IR) ? w_ih[(size_t)j * IR + k]     : 0.0f;
                b = (k + 1 < IR) ? w_ih[(size_t)j * IR + k + 1] : 0.0f;
            } else {
                int k = (q - 2) * 32 + kk;
                a = w_hh[(size_t)j * 64 + k];
                b = w_hh[(size_t)j * 64 + k + 1];
            }
            w[c][kk / 2] = pack2(a * sc, b * sc);
        }
    }
    uint64_t bias[2];
#pragma unroll
    for (int c = 0; c < 2; c++) {
        const int j = p + c * 128;
        const float sc = c ? scB : scA;
        bias[c] = (q == 0) ? pack2((b_ih[j] + b_hh[j]) * sc, 0.0f) : 0ull;
    }

    // h0 = c0 = 0; stage x(0)
    for (int i = tid; i < BT * 64; i += 512) { s_h[i] = 0.0f; s_c[i] = 0.0f; }
    if (tid < BT * 16)
        ((float4*)s_x)[tid] = ((const float4*)(in + (size_t)b0 * 64))[tid];
    __syncthreads();

    for (int t = 0; t < TT; t++) {
        const int cur = t & 1, nxt = cur ^ 1;
        const float* ap = (q < 2) ? (s_x + cur * BT * 64 + q * 32)
                                  : (s_h + (q - 2) * 32);

        // prefetch x(t+1) into regs (latency hidden under phase-1 ML)
        float4 pf;
        const bool do_pf = (t + 1 < TT) && (tid < BT * 16);
        if (do_pf)
            pf = ((const float4*)(in + ((size_t)(t + 1) * BP + b0) * 64))[tid];

        // ---- ML chunk: rows [rs, rs+rn), rn <= 4 ----
        auto ml_rows = [&](int rs, int rn) {
            uint64_t accA[4], accB[4];
#pragma unroll
            for (int r = 0; r < 4; r++) { accA[r] = bias[0]; accB[r] = bias[1]; }
#pragma unroll
            for (int kk = 0; kk < 32; kk += 4) {
#pragma unroll
                for (int r = 0; r < 4; r++) {
                    if (r < rn) {
                        ulonglong2 v = *(const ulonglong2*)(ap + (size_t)(rs + r) * 64 + kk);
                        ffma2(accA[r], v.x, w[0][kk / 2]);
                        ffma2(accA[r], v.y, w[0][kk / 2 + 1]);
                        ffma2(accB[r], v.x, w[1][kk / 2]);
                        ffma2(accB[r], v.y, w[1][kk / 2 + 1]);
                    }
                }
            }
#pragma unroll
            for (int r = 0; r < 4; r++) {
                if (r < rn) {
                    s_gp[(size_t)((glo)     * 4 + q) * BT * 64 + (rs + r) * 64 + u] = hsum2(accA[r]);
                    s_gp[(size_t)((2 + glo) * 4 + q) * BT * 64 + (rs + r) * 64 + u] = hsum2(accB[r]);
                }
            }
        };

        // ---- EW: 7 rows starting at rs; threads 0..447, 1 unit each ----
        auto ew_rows = [&](int rs) {
            if (tid < 448) {
                const int r  = rs + (tid >> 6);
                const int uu = tid & 63;
                float gi = 0.f, gf = 0.f, gg = 0.f, go = 0.f;
#pragma unroll
                for (int qq = 0; qq < 4; qq++) {
                    const float* gpb = s_gp + (size_t)qq * BT * 64 + r * 64 + uu;
                    gi += gpb[0 * 4 * BT * 64];
                    gf += gpb[1 * 4 * BT * 64];
                    gg += gpb[2 * 4 * BT * 64];
                    go += gpb[3 * 4 * BT * 64];
                }
                // gi,gf,go prescaled by log2e; gg prescaled by 2*log2e
                float iv = sigm2(gi), fv = sigm2(gf), gv = tanh2(gg), ov = sigm2(go);
                float cc = fmaf(fv, s_c[r * 64 + uu], iv * gv);
                float hh = ov * tanh2(2.0f * LOG2E * cc);
                s_c[r * 64 + uu] = cc;
                s_h[r * 64 + uu] = hh;
                out[((size_t)t * BP + b0 + r) * 64 + uu] = hh;
            }
        };

        // ---- phase 1: ML rows 0-6; commit x(t+1) (s_x[nxt] is dead here) ----
        ml_rows(0, 4);
        ml_rows(4, 3);
        if (do_pf)
            ((float4*)(s_x + nxt * BT * 64))[tid] = pf;
        __syncthreads();                 // A: partials rows 0-6 ready

        // ---- phase 2: ML rows 7-13 || EW rows 0-6 (disjoint s_h rows) ----
        ml_rows(7, 4);
        ml_rows(11, 3);
        ew_rows(0);
        __syncthreads();                 // B: partials rows 7-13 ready; h 0-6 final

        // ---- phase 3: EW rows 7-13 ----
        ew_rows(7);
        __syncthreads();                 // C: h complete; x(t+1) staged
    }
}

// ---------------------------------------------------------------------------
// Output MLP: h[T,BP,64] -> relu(h@wo1^T+bo1)@wo2^T+bo2 -> out[B,T,4]
// ---------------------------------------------------------------------------
__global__ void mlp_out_kernel(int insel,
                               const float* __restrict__ wo1, const float* __restrict__ bo1,
                               const float* __restrict__ wo2, const float* __restrict__ bo2,
                               float* __restrict__ outp)
{
    __shared__ float s_w1[32][64];
    __shared__ float s_b1[32];
    __shared__ float s_w2[4][32];
    __shared__ float s_b2[4];
    int tid = threadIdx.x;
    for (int i = tid; i < 32 * 64; i += 256) s_w1[i / 64][i % 64] = wo1[i];
    if (tid < 32) s_b1[tid] = bo1[tid];
    if (tid < 128) s_w2[tid / 32][tid % 32] = wo2[tid];
    if (tid < 4) s_b2[tid] = bo2[tid];
    __syncthreads();

    const float* in = bufptr(insel);
    int idx = blockIdx.x * blockDim.x + tid;   // idx = t*B + b (coalesced h reads)
    int t = idx / BB;
    int b = idx % BB;

    float h[64];
    const float4* src = reinterpret_cast<const float4*>(in + ((size_t)t * BP + b) * 64);
#pragma unroll
    for (int i = 0; i < 16; i++) {
        float4 v = src[i];
        h[4 * i + 0] = v.x; h[4 * i + 1] = v.y; h[4 * i + 2] = v.z; h[4 * i + 3] = v.w;
    }

    float h2[32];
#pragma unroll
    for (int j = 0; j < 32; j++) {
        float o = s_b1[j];
#pragma unroll
        for (int k = 0; k < 64; k++) o = fmaf(s_w1[j][k], h[k], o);
        h2[j] = fmaxf(o, 0.0f);
    }
    float* dst = outp + ((size_t)b * TT + t) * 4;
#pragma unroll
    for (int j = 0; j < 4; j++) {
        float o = s_b2[j];
#pragma unroll
        for (int k = 0; k < 32; k++) o = fmaf(s_w2[j][k], h2[k], o);
        dst[j] = o;
    }
}

// ---------------------------------------------------------------------------
extern "C" void kernel_launch(void* const* d_in, const int* in_sizes, int n_in,
                              void* d_out, int out_size)
{
    const float* x     = (const float*)d_in[0];
    const float* w1    = (const float*)d_in[1];
    const float* b1    = (const float*)d_in[2];
    const float* w2    = (const float*)d_in[3];
    const float* b2    = (const float*)d_in[4];
    const float* w_ih0 = (const float*)d_in[5];
    const float* w_hh0 = (const float*)d_in[6];
    const float* b_ih0 = (const float*)d_in[7];
    const float* b_hh0 = (const float*)d_in[8];
    const float* w_ih  = (const float*)d_in[9];   // (7, 256, 64)
    const float* w_hh  = (const float*)d_in[10];  // (7, 256, 64)
    const float* b_ih  = (const float*)d_in[11];  // (7, 256)
    const float* b_hh  = (const float*)d_in[12];  // (7, 256)
    const float* wo1   = (const float*)d_in[13];
    const float* bo1   = (const float*)d_in[14];
    const float* wo2   = (const float*)d_in[15];
    const float* bo2   = (const float*)d_in[16];
    float* outp = (float*)d_out;

    const int smem_sz = (2 * BT * 64 + 2 * BT * 64 + 16 * BT * 64) * 4;  // 71680 B
    cudaFuncSetAttribute(lstm_fused<16>, cudaFuncAttributeMaxDynamicSharedMemorySize, smem_sz);
    cudaFuncSetAttribute(lstm_fused<64>, cudaFuncAttributeMaxDynamicSharedMemorySize, smem_sz);

    const int nelem = BB * TT;               // 131072

    mlp_in_kernel<<<nelem / 256, 256>>>(x, w1, b1, w2, b2);

    // layer 0: A -> B (x cols 16-63 are zero; IR=16 weights)
    lstm_fused<16><<<NCTA, 512, smem_sz>>>(0, 1, w_ih0, w_hh0, b_ih0, b_hh0);

    // layers 1..7: ping-pong B->A->B->...
    int cur = 1;
    for (int l = 0; l < NL - 1; l++) {
        int nxt = cur ^ 1;
        lstm_fused<64><<<NCTA, 512, smem_sz>>>(cur, nxt,
                                               w_ih + (size_t)l * GG * HH,
                                               w_hh + (size_t)l * GG * HH,
                                               b_ih + (size_t)l * GG,
                                               b_hh + (size_t)l * GG);
        cur = nxt;
    }

    mlp_out_kernel<<<nelem / 256, 256>>>(cur, wo1, bo1, wo2, bo2, outp);
}

// round 13
// speedup vs baseline: 1.2154x; 1.0598x over previous
#include <cuda_runtime.h>
#include <cuda_bf16.h>
#include <cstdint>

// Problem constants
#define BB 2048   // batch
#define BP 2058   // padded batch (147 CTAs * 14 rows)
#define TT 64     // timesteps
#define HH 64     // LSTM hidden
#define GG 256    // 4*H gates
#define NL 8      // LSTM layers
#define BT 14     // batch rows per CTA
#define NCTA 147

// Ping-pong inter-layer buffers, layout [T, BP, 64] (layer0 x: cols 0-15, rest zero)
__device__ float g_bufA[(size_t)TT * BP * HH + 256];
__device__ float g_bufB[(size_t)TT * BP * HH + 256];

__device__ __forceinline__ float sigm(float x) {
    return __fdividef(1.0f, 1.0f + __expf(-x));
}
__device__ __forceinline__ float tanh_(float x) {
    return __fdividef(2.0f, 1.0f + __expf(-2.0f * x)) - 1.0f;
}

// ---- packed f32x2 helpers (Blackwell FFMA2; PTX-only) ----
__device__ __forceinline__ void ffma2(uint64_t& d, uint64_t a, uint64_t b) {
    asm("fma.rn.f32x2 %0, %1, %2, %0;" : "+l"(d) : "l"(a), "l"(b));
}
__device__ __forceinline__ uint64_t pack2(float lo, float hi) {
    uint64_t r;
    asm("mov.b64 %0, {%1, %2};" : "=l"(r) : "f"(lo), "f"(hi));
    return r;
}
__device__ __forceinline__ float hsum2(uint64_t v) {
    float lo, hi;
    asm("mov.b64 {%0, %1}, %2;" : "=f"(lo), "=f"(hi) : "l"(v));
    return lo + hi;
}

// ---------------------------------------------------------------------------
// Whole-model persistent kernel. 147 CTAs x 512 threads; each CTA owns 14
// batch rows end-to-end (input MLP -> 8 LSTM layers -> output MLP). The model
// is batch-row-local, so no cross-CTA sync is ever needed; layer boundaries
// are __syncthreads(). LSTM step = R8's proven 3-phase schedule:
//   [ML rows0-7] bar [ML rows8-13 || EW rows0-7] bar [EW rows8-13 + x commit] bar
// Weights (2 cols x 32 ks = 32 u64) reloaded into regs per layer.
// ---------------------------------------------------------------------------
__global__ void __launch_bounds__(512, 1)
model_kernel(const float* __restrict__ x_in,
             const float* __restrict__ w1, const float* __restrict__ b1,
             const float* __restrict__ w2, const float* __restrict__ b2,
             const float* __restrict__ w_ih0, const float* __restrict__ w_hh0,
             const float* __restrict__ b_ih0, const float* __restrict__ b_hh0,
             const float* __restrict__ w_ih, const float* __restrict__ w_hh,
             const float* __restrict__ b_ih, const float* __restrict__ b_hh,
             const float* __restrict__ wo1, const float* __restrict__ bo1,
             const float* __restrict__ wo2, const float* __restrict__ bo2,
             float* __restrict__ outp)
{
    extern __shared__ float smem[];
    float* s_x   = smem;                  // [2][BT][64]
    float* s_h   = s_x + 2 * BT * 64;     // [BT][64]
    float* s_c   = s_h + BT * 64;         // [BT][64]
    float* s_gp  = s_c + BT * 64;         // [16][BT][64]  plane = gate*4+q
    float* s_mw  = s_gp + 16 * BT * 64;   // mlp-in w1[32],b1[16],w2[256],b2[16] = 320
    float* s_ow1 = s_mw + 320;            // [32][64]
    float* s_ob1 = s_ow1 + 2048;          // [32]
    float* s_ow2 = s_ob1 + 32;            // [4][32]
    float* s_ob2 = s_ow2 + 128;           // [4]

    const int tid = threadIdx.x;
    const int p   = tid & 127;            // column pair
    const int q   = tid >> 7;             // K split 0..3
    const int b0  = blockIdx.x * BT;
    const int glo = p >> 6;               // gate of jA: 0=i, 1=f
    const int u   = p & 63;               // unit

    // ---- load MLP weights into smem ----
    if (tid < 32)  s_mw[tid] = w1[tid];               // w1
    if (tid < 16)  s_mw[32 + tid] = b1[tid];          // b1
    if (tid >= 64 && tid < 64 + 256) s_mw[48 + (tid - 64)] = w2[tid - 64];   // w2
    if (tid >= 320 && tid < 336) s_mw[304 + (tid - 320)] = b2[tid - 320];    // b2
    for (int i = tid; i < 2048; i += 512) s_ow1[i] = wo1[i];
    if (tid < 32) s_ob1[tid] = bo1[tid];
    if (tid < 128) s_ow2[tid] = wo2[tid];
    if (tid < 4) s_ob2[tid] = bo2[tid];
    __syncthreads();

    // ---- prologue: input MLP for own rows -> g_bufA[t][b0..b0+13][0..63] ----
    {
        const float* mw1 = s_mw;          // [16][2]
        const float* mb1 = s_mw + 32;
        const float* mw2 = s_mw + 48;     // [16][16]
        const float* mb2 = s_mw + 304;
        for (int pass = 0; pass < 2; pass++) {
            int idx = pass * 512 + tid;   // 0..895 (r*64 + t)
            if (idx < BT * TT) {
                int r = idx >> 6;
                int t = idx & 63;
                int b = b0 + r;
                float x0 = 0.f, x1 = 0.f;
                if (b < BB) {
                    x0 = x_in[((size_t)b * TT + t) * 2 + 0];
                    x1 = x_in[((size_t)b * TT + t) * 2 + 1];
                }
                float h1[16];
#pragma unroll
                for (int j = 0; j < 16; j++) {
                    float v = fmaf(mw1[j * 2], x0, fmaf(mw1[j * 2 + 1], x1, mb1[j]));
                    h1[j] = fmaxf(v, 0.0f);
                }
                float o[16];
#pragma unroll
                for (int j = 0; j < 16; j++) {
                    float s = mb2[j];
#pragma unroll
                    for (int k = 0; k < 16; k++) s = fmaf(mw2[j * 16 + k], h1[k], s);
                    o[j] = s;
                }
                float4* dst = (float4*)(g_bufA + ((size_t)t * BP + b) * 64);
#pragma unroll
                for (int j = 0; j < 4; j++)
                    dst[j] = make_float4(o[4 * j], o[4 * j + 1], o[4 * j + 2], o[4 * j + 3]);
                float4 z = make_float4(0.f, 0.f, 0.f, 0.f);
#pragma unroll
                for (int j = 4; j < 16; j++) dst[j] = z;
            }
        }
    }

    // ---- layer loop ----
    int cur_in = 0;
    for (int l = 0; l < NL; l++) {
        const float* in  = cur_in ? g_bufB : g_bufA;
        float*       out = cur_in ? g_bufA : g_bufB;

        // load this layer's weights into regs (2 cols x 32 ks as u64 pairs)
        uint64_t w[2][16];
        uint64_t bias[2];
#pragma unroll
        for (int c = 0; c < 2; c++) {
            const int j = p + c * 128;
#pragma unroll
            for (int kk = 0; kk < 32; kk += 2) {
                float a, b;
                if (q < 2) {
                    int k = q * 32 + kk;
                    if (l == 0) {
                        a = (k < 16)     ? w_ih0[(size_t)j * 16 + k]     : 0.0f;
                        b = (k + 1 < 16) ? w_ih0[(size_t)j * 16 + k + 1] : 0.0f;
                    } else {
                        const float* wih = w_ih + (size_t)(l - 1) * GG * HH;
                        a = wih[(size_t)j * 64 + k];
                        b = wih[(size_t)j * 64 + k + 1];
                    }
                } else {
                    int k = (q - 2) * 32 + kk;
                    const float* whh = (l == 0) ? w_hh0 : w_hh + (size_t)(l - 1) * GG * HH;
                    a = whh[(size_t)j * 64 + k];
                    b = whh[(size_t)j * 64 + k + 1];
                }
                w[c][kk / 2] = pack2(a, b);
            }
            const float* bi = (l == 0) ? b_ih0 : b_ih + (size_t)(l - 1) * GG;
            const float* bh = (l == 0) ? b_hh0 : b_hh + (size_t)(l - 1) * GG;
            bias[c] = (q == 0) ? pack2(bi[j] + bh[j], 0.0f) : 0ull;
        }

        // h0 = c0 = 0; stage x(0)
        for (int i = tid; i < BT * 64; i += 512) { s_h[i] = 0.0f; s_c[i] = 0.0f; }
        __syncthreads();   // also guards: prologue/prev-layer writes visible for x(0)
        if (tid < BT * 16)
            ((float4*)s_x)[tid] = ((const float4*)(in + (size_t)b0 * 64))[tid];
        __syncthreads();

        for (int t = 0; t < TT; t++) {
            const int cur = t & 1, nxt = cur ^ 1;
            const float* ap = (q < 2) ? (s_x + cur * BT * 64 + q * 32)
                                      : (s_h + (q - 2) * 32);

            // prefetch x(t+1) into regs (hidden under mainloop)
            float4 pf;
            const bool do_pf = (t + 1 < TT) && (tid < BT * 16);
            if (do_pf)
                pf = ((const float4*)(in + ((size_t)(t + 1) * BP + b0) * 64))[tid];

            // ---- ML chunk: rows [rs, rs+rn), rn <= 4 ----
            auto ml_rows = [&](int rs, int rn) {
                uint64_t accA[4], accB[4];
#pragma unroll
                for (int r = 0; r < 4; r++) { accA[r] = bias[0]; accB[r] = bias[1]; }
#pragma unroll
                for (int kk = 0; kk < 32; kk += 4) {
#pragma unroll
                    for (int r = 0; r < 4; r++) {
                        if (r < rn) {
                            ulonglong2 v = *(const ulonglong2*)(ap + (size_t)(rs + r) * 64 + kk);
                            ffma2(accA[r], v.x, w[0][kk / 2]);
                            ffma2(accA[r], v.y, w[0][kk / 2 + 1]);
                            ffma2(accB[r], v.x, w[1][kk / 2]);
                            ffma2(accB[r], v.y, w[1][kk / 2 + 1]);
                        }
                    }
                }
#pragma unroll
                for (int r = 0; r < 4; r++) {
                    if (r < rn) {
                        s_gp[(size_t)((glo)     * 4 + q) * BT * 64 + (rs + r) * 64 + u] = hsum2(accA[r]);
                        s_gp[(size_t)((2 + glo) * 4 + q) * BT * 64 + (rs + r) * 64 + u] = hsum2(accB[r]);
                    }
                }
            };

            // ---- EW: unit ul for this thread within rows [rs, rs+rn) ----
            auto ew_rows = [&](int rs, int nunits) {
                if (tid < nunits) {
                    const int r  = rs + (tid >> 6);
                    const int uu = tid & 63;
                    float gi = 0.f, gf = 0.f, gg = 0.f, go = 0.f;
#pragma unroll
                    for (int qq = 0; qq < 4; qq++) {
                        const float* gpb = s_gp + (size_t)qq * BT * 64 + r * 64 + uu;
                        gi += gpb[0 * 4 * BT * 64];
                        gf += gpb[1 * 4 * BT * 64];
                        gg += gpb[2 * 4 * BT * 64];
                        go += gpb[3 * 4 * BT * 64];
                    }
                    float iv = sigm(gi), fv = sigm(gf), gv = tanh_(gg), ov = sigm(go);
                    float cc = fmaf(fv, s_c[r * 64 + uu], iv * gv);
                    float hh = ov * tanh_(cc);
                    s_c[r * 64 + uu] = cc;
                    s_h[r * 64 + uu] = hh;
                    out[((size_t)t * BP + b0 + r) * 64 + uu] = hh;
                }
            };

            ml_rows(0, 4);
            ml_rows(4, 4);
            __syncthreads();                 // A: partials rows 0-7 ready
            ml_rows(8, 4);
            ml_rows(12, 2);
            ew_rows(0, 512);                 // EW rows 0-7 (512 units)
            __syncthreads();                 // B: partials rows 8-13; h rows 0-7 final
            ew_rows(8, 384);                 // EW rows 8-13 (384 units)
            if (do_pf)
                ((float4*)(s_x + nxt * BT * 64))[tid] = pf;
            __syncthreads();                 // C: h complete, x(t+1) staged
        }
        cur_in ^= 1;
        __syncthreads();                     // layer writes visible to own CTA
    }

    // ---- epilogue: output MLP for own rows ----
    {
        const float* fin = cur_in ? g_bufB : g_bufA;   // final h buffer
        for (int pass = 0; pass < 2; pass++) {
            int idx = pass * 512 + tid;      // r*64 + t
            if (idx < BT * TT) {
                int r = idx >> 6;
                int t = idx & 63;
                int b = b0 + r;
                if (b < BB) {
                    float h[64];
                    const float4* src = (const float4*)(fin + ((size_t)t * BP + b) * 64);
#pragma unroll
                    for (int i = 0; i < 16; i++) {
                        float4 v = src[i];
                        h[4 * i + 0] = v.x; h[4 * i + 1] = v.y;
                        h[4 * i + 2] = v.z; h[4 * i + 3] = v.w;
                    }
                    float h2[32];
#pragma unroll
                    for (int j = 0; j < 32; j++) {
                        float o = s_ob1[j];
#pragma unroll
                        for (int k = 0; k < 64; k++) o = fmaf(s_ow1[j * 64 + k], h[k], o);
                        h2[j] = fmaxf(o, 0.0f);
                    }
                    float o[4];
#pragma unroll
                    for (int j = 0; j < 4; j++) {
                        float s = s_ob2[j];
#pragma unroll
                        for (int k = 0; k < 32; k++) s = fmaf(s_ow2[j * 32 + k], h2[k], s);
                        o[j] = s;
                    }
                    *(float4*)(outp + ((size_t)b * TT + t) * 4) =
                        make_float4(o[0], o[1], o[2], o[3]);
                }
            }
        }
    }
}

// ---------------------------------------------------------------------------
extern "C" void kernel_launch(void* const* d_in, const int* in_sizes, int n_in,
                              void* d_out, int out_size)
{
    const float* x     = (const float*)d_in[0];
    const float* w1    = (const float*)d_in[1];
    const float* b1    = (const float*)d_in[2];
    const float* w2    = (const float*)d_in[3];
    const float* b2    = (const float*)d_in[4];
    const float* w_ih0 = (const float*)d_in[5];
    const float* w_hh0 = (const float*)d_in[6];
    const float* b_ih0 = (const float*)d_in[7];
    const float* b_hh0 = (const float*)d_in[8];
    const float* w_ih  = (const float*)d_in[9];   // (7, 256, 64)
    const float* w_hh  = (const float*)d_in[10];  // (7, 256, 64)
    const float* b_ih  = (const float*)d_in[11];  // (7, 256)
    const float* b_hh  = (const float*)d_in[12];  // (7, 256)
    const float* wo1   = (const float*)d_in[13];
    const float* bo1   = (const float*)d_in[14];
    const float* wo2   = (const float*)d_in[15];
    const float* bo2   = (const float*)d_in[16];
    float* outp = (float*)d_out;

    // smem: lstm working set + mlp weights
    const int smem_sz = (20 * BT * 64 + 320 + 2048 + 32 + 128 + 4) * 4;  // 81808 B
    cudaFuncSetAttribute(model_kernel, cudaFuncAttributeMaxDynamicSharedMemorySize, smem_sz);

    model_kernel<<<NCTA, 512, smem_sz>>>(x, w1, b1, w2, b2,
                                         w_ih0, w_hh0, b_ih0, b_hh0,
                                         w_ih, w_hh, b_ih, b_hh,
                                         wo1, bo1, wo2, bo2, outp);
}

// round 14
// speedup vs baseline: 1.2285x; 1.0108x over previous
#include <cuda_runtime.h>
#include <cuda_bf16.h>
#include <cstdint>

// Problem constants
#define BB 2048   // batch
#define BP 2058   // padded batch (147 CTAs * 14 rows)
#define TT 64     // timesteps
#define HH 64     // LSTM hidden
#define GG 256    // 4*H gates
#define NL 8      // LSTM layers
#define BT 14     // batch rows per CTA
#define NCTA 147

// Ping-pong inter-layer buffers, layout [T, BP, 64] (layer0 x: cols 0-15, rest zero)
__device__ float g_bufA[(size_t)TT * BP * HH + 256];
__device__ float g_bufB[(size_t)TT * BP * HH + 256];

__device__ __forceinline__ float sigm(float x) {
    return __fdividef(1.0f, 1.0f + __expf(-x));
}
__device__ __forceinline__ float tanh_(float x) {
    return __fdividef(2.0f, 1.0f + __expf(-2.0f * x)) - 1.0f;
}

// ---- packed f32x2 helpers (Blackwell FFMA2; PTX-only) ----
__device__ __forceinline__ void ffma2(uint64_t& d, uint64_t a, uint64_t b) {
    asm("fma.rn.f32x2 %0, %1, %2, %0;" : "+l"(d) : "l"(a), "l"(b));
}
__device__ __forceinline__ uint64_t pack2(float lo, float hi) {
    uint64_t r;
    asm("mov.b64 %0, {%1, %2};" : "=l"(r) : "f"(lo), "f"(hi));
    return r;
}
__device__ __forceinline__ float hsum2(uint64_t v) {
    float lo, hi;
    asm("mov.b64 {%0, %1}, %2;" : "=f"(lo), "=f"(hi) : "l"(v));
    return lo + hi;
}

// ---------------------------------------------------------------------------
// Whole-model persistent kernel; 147 CTAs x 512 threads; each CTA owns 14
// batch rows end-to-end. LSTM step uses a cross-step 2-barrier schedule in
// which EW is never exposed:
//   P1: ML(t) rows 8-13  || EW(t) rows 0-7                       -> bar
//   P2: ML(t+1) rows 0-7 || EW(t) rows 8-13 || x(t+2) commit     -> bar
// (ml_rows(rs,rn) reads h rows rs.. only and writes gp rows rs.. only, so
// every concurrent pair above touches disjoint smem row ranges.)
// ---------------------------------------------------------------------------
__global__ void __launch_bounds__(512, 1)
model_kernel(const float* __restrict__ x_in,
             const float* __restrict__ w1, const float* __restrict__ b1,
             const float* __restrict__ w2, const float* __restrict__ b2,
             const float* __restrict__ w_ih0, const float* __restrict__ w_hh0,
             const float* __restrict__ b_ih0, const float* __restrict__ b_hh0,
             const float* __restrict__ w_ih, const float* __restrict__ w_hh,
             const float* __restrict__ b_ih, const float* __restrict__ b_hh,
             const float* __restrict__ wo1, const float* __restrict__ bo1,
             const float* __restrict__ wo2, const float* __restrict__ bo2,
             float* __restrict__ outp)
{
    extern __shared__ float smem[];
    float* s_x   = smem;                  // [2][BT][64]
    float* s_h   = s_x + 2 * BT * 64;     // [BT][64]
    float* s_c   = s_h + BT * 64;         // [BT][64]
    float* s_gp  = s_c + BT * 64;         // [16][BT][64]  plane = gate*4+q
    float* s_mw  = s_gp + 16 * BT * 64;   // mlp-in w1[32],b1[16],w2[256],b2[16]
    float* s_ow1 = s_mw + 320;            // [32][64]
    float* s_ob1 = s_ow1 + 2048;          // [32]
    float* s_ow2 = s_ob1 + 32;            // [4][32]
    float* s_ob2 = s_ow2 + 128;           // [4]

    const int tid = threadIdx.x;
    const int p   = tid & 127;            // column pair
    const int q   = tid >> 7;             // K split 0..3
    const int b0  = blockIdx.x * BT;
    const int glo = p >> 6;               // gate of jA: 0=i, 1=f
    const int u   = p & 63;               // unit

    // ---- load MLP weights into smem ----
    if (tid < 32)  s_mw[tid] = w1[tid];
    if (tid < 16)  s_mw[32 + tid] = b1[tid];
    if (tid >= 64 && tid < 64 + 256) s_mw[48 + (tid - 64)] = w2[tid - 64];
    if (tid >= 320 && tid < 336) s_mw[304 + (tid - 320)] = b2[tid - 320];
    for (int i = tid; i < 2048; i += 512) s_ow1[i] = wo1[i];
    if (tid < 32) s_ob1[tid] = bo1[tid];
    if (tid < 128) s_ow2[tid] = wo2[tid];
    if (tid < 4) s_ob2[tid] = bo2[tid];
    __syncthreads();

    // ---- prologue: input MLP for own rows -> g_bufA[t][b0..b0+13][0..63] ----
    {
        const float* mw1 = s_mw;
        const float* mb1 = s_mw + 32;
        const float* mw2 = s_mw + 48;
        const float* mb2 = s_mw + 304;
        for (int pass = 0; pass < 2; pass++) {
            int idx = pass * 512 + tid;   // r*64 + t
            if (idx < BT * TT) {
                int r = idx >> 6;
                int t = idx & 63;
                int b = b0 + r;
                float x0 = 0.f, x1 = 0.f;
                if (b < BB) {
                    x0 = x_in[((size_t)b * TT + t) * 2 + 0];
                    x1 = x_in[((size_t)b * TT + t) * 2 + 1];
                }
                float h1[16];
#pragma unroll
                for (int j = 0; j < 16; j++) {
                    float v = fmaf(mw1[j * 2], x0, fmaf(mw1[j * 2 + 1], x1, mb1[j]));
                    h1[j] = fmaxf(v, 0.0f);
                }
                float o[16];
#pragma unroll
                for (int j = 0; j < 16; j++) {
                    float s = mb2[j];
#pragma unroll
                    for (int k = 0; k < 16; k++) s = fmaf(mw2[j * 16 + k], h1[k], s);
                    o[j] = s;
                }
                float4* dst = (float4*)(g_bufA + ((size_t)t * BP + b) * 64);
#pragma unroll
                for (int j = 0; j < 4; j++)
                    dst[j] = make_float4(o[4 * j], o[4 * j + 1], o[4 * j + 2], o[4 * j + 3]);
                float4 z = make_float4(0.f, 0.f, 0.f, 0.f);
#pragma unroll
                for (int j = 4; j < 16; j++) dst[j] = z;
            }
        }
    }

    // ---- layer loop ----
    int cur_in = 0;
    for (int l = 0; l < NL; l++) {
        const float* in  = cur_in ? g_bufB : g_bufA;
        float*       out = cur_in ? g_bufA : g_bufB;

        // load this layer's weights into regs (2 cols x 32 ks as u64 pairs)
        uint64_t w[2][16];
        uint64_t bias[2];
#pragma unroll
        for (int c = 0; c < 2; c++) {
            const int j = p + c * 128;
#pragma unroll
            for (int kk = 0; kk < 32; kk += 2) {
                float a, b;
                if (q < 2) {
                    int k = q * 32 + kk;
                    if (l == 0) {
                        a = (k < 16)     ? w_ih0[(size_t)j * 16 + k]     : 0.0f;
                        b = (k + 1 < 16) ? w_ih0[(size_t)j * 16 + k + 1] : 0.0f;
                    } else {
                        const float* wih = w_ih + (size_t)(l - 1) * GG * HH;
                        a = wih[(size_t)j * 64 + k];
                        b = wih[(size_t)j * 64 + k + 1];
                    }
                } else {
                    int k = (q - 2) * 32 + kk;
                    const float* whh = (l == 0) ? w_hh0 : w_hh + (size_t)(l - 1) * GG * HH;
                    a = whh[(size_t)j * 64 + k];
                    b = whh[(size_t)j * 64 + k + 1];
                }
                w[c][kk / 2] = pack2(a, b);
            }
            const float* bi = (l == 0) ? b_ih0 : b_ih + (size_t)(l - 1) * GG;
            const float* bh = (l == 0) ? b_hh0 : b_hh + (size_t)(l - 1) * GG;
            bias[c] = (q == 0) ? pack2(bi[j] + bh[j], 0.0f) : 0ull;
        }

        // ---- ML chunk for given x-slot: rows [rs, rs+rn), rn <= 4 ----
        auto ml_rows = [&](const float* ap, int rs, int rn) {
            uint64_t accA[4], accB[4];
#pragma unroll
            for (int r = 0; r < 4; r++) { accA[r] = bias[0]; accB[r] = bias[1]; }
#pragma unroll
            for (int kk = 0; kk < 32; kk += 4) {
#pragma unroll
                for (int r = 0; r < 4; r++) {
                    if (r < rn) {
                        ulonglong2 v = *(const ulonglong2*)(ap + (size_t)(rs + r) * 64 + kk);
                        ffma2(accA[r], v.x, w[0][kk / 2]);
                        ffma2(accA[r], v.y, w[0][kk / 2 + 1]);
                        ffma2(accB[r], v.x, w[1][kk / 2]);
                        ffma2(accB[r], v.y, w[1][kk / 2 + 1]);
                    }
                }
            }
#pragma unroll
            for (int r = 0; r < 4; r++) {
                if (r < rn) {
                    s_gp[(size_t)((glo)     * 4 + q) * BT * 64 + (rs + r) * 64 + u] = hsum2(accA[r]);
                    s_gp[(size_t)((2 + glo) * 4 + q) * BT * 64 + (rs + r) * 64 + u] = hsum2(accB[r]);
                }
            }
        };

        // ---- EW: rows [rs, ...), nunits threads, 1 unit each ----
        auto ew_rows = [&](int rs, int nunits, int t) {
            if (tid < nunits) {
                const int r  = rs + (tid >> 6);
                const int uu = tid & 63;
                float gi = 0.f, gf = 0.f, gg = 0.f, go = 0.f;
#pragma unroll
                for (int qq = 0; qq < 4; qq++) {
                    const float* gpb = s_gp + (size_t)qq * BT * 64 + r * 64 + uu;
                    gi += gpb[0 * 4 * BT * 64];
                    gf += gpb[1 * 4 * BT * 64];
                    gg += gpb[2 * 4 * BT * 64];
                    go += gpb[3 * 4 * BT * 64];
                }
                float iv = sigm(gi), fv = sigm(gf), gv = tanh_(gg), ov = sigm(go);
                float cc = fmaf(fv, s_c[r * 64 + uu], iv * gv);
                float hh = ov * tanh_(cc);
                s_c[r * 64 + uu] = cc;
                s_h[r * 64 + uu] = hh;
                out[((size_t)t * BP + b0 + r) * 64 + uu] = hh;
            }
        };

        // per-layer prologue: h0=c0=0; stage x(0); ML(0) rows 0-7; stage x(1)
        for (int i = tid; i < BT * 64; i += 512) { s_h[i] = 0.0f; s_c[i] = 0.0f; }
        __syncthreads();   // prev-layer gmem writes visible; h/c zeroed
        if (tid < BT * 16)
            ((float4*)s_x)[tid] = ((const float4*)(in + (size_t)b0 * 64))[tid];
        __syncthreads();
        {
            float4 pf1;
            if (tid < BT * 16)
                pf1 = ((const float4*)(in + ((size_t)BP + b0) * 64))[tid];
            const float* ap0 = (q < 2) ? (s_x + q * 32) : (s_h + (q - 2) * 32);
            ml_rows(ap0, 0, 4);
            ml_rows(ap0, 4, 4);
            if (tid < BT * 16)
                ((float4*)(s_x + BT * 64))[tid] = pf1;
        }
        __syncthreads();   // partials(0) rows 0-7 ready; x(1) staged

        for (int t = 0; t < TT; t++) {
            const int cur = t & 1, nxt = cur ^ 1;
            const float* ap_cur = (q < 2) ? (s_x + cur * BT * 64 + q * 32)
                                          : (s_h + (q - 2) * 32);
            const float* ap_nxt = (q < 2) ? (s_x + nxt * BT * 64 + q * 32)
                                          : (s_h + (q - 2) * 32);

            // prefetch x(t+2) into regs (hidden under P1)
            float4 pf;
            const bool do_pf = (t + 2 < TT) && (tid < BT * 16);
            if (do_pf)
                pf = ((const float4*)(in + ((size_t)(t + 2) * BP + b0) * 64))[tid];

            // ---- P1: ML(t) rows 8-13 || EW(t) rows 0-7 ----
            ml_rows(ap_cur, 8, 4);
            ml_rows(ap_cur, 12, 2);
            ew_rows(0, 512, t);
            __syncthreads();   // partials(t) rows 8-13 ready; h(t) rows 0-7 final

            // ---- P2: ML(t+1) rows 0-7 || EW(t) rows 8-13 || x(t+2) commit ----
            if (t + 1 < TT) {
                ml_rows(ap_nxt, 0, 4);
                ml_rows(ap_nxt, 4, 4);
            }
            ew_rows(8, 384, t);
            if (do_pf)
                ((float4*)(s_x + cur * BT * 64))[tid] = pf;   // x(t) dead
            __syncthreads();   // partials(t+1) rows 0-7 ready; h(t) complete
        }
        cur_in ^= 1;
    }

    // ---- epilogue: output MLP for own rows ----
    {
        const float* fin = cur_in ? g_bufB : g_bufA;
        for (int pass = 0; pass < 2; pass++) {
            int idx = pass * 512 + tid;      // r*64 + t
            if (idx < BT * TT) {
                int r = idx >> 6;
                int t = idx & 63;
                int b = b0 + r;
                if (b < BB) {
                    float h[64];
                    const float4* src = (const float4*)(fin + ((size_t)t * BP + b) * 64);
#pragma unroll
                    for (int i = 0; i < 16; i++) {
                        float4 v = src[i];
                        h[4 * i + 0] = v.x; h[4 * i + 1] = v.y;
                        h[4 * i + 2] = v.z; h[4 * i + 3] = v.w;
                    }
                    float h2[32];
#pragma unroll
                    for (int j = 0; j < 32; j++) {
                        float o = s_ob1[j];
#pragma unroll
                        for (int k = 0; k < 64; k++) o = fmaf(s_ow1[j * 64 + k], h[k], o);
                        h2[j] = fmaxf(o, 0.0f);
                    }
                    float o[4];
#pragma unroll
                    for (int j = 0; j < 4; j++) {
                        float s = s_ob2[j];
#pragma unroll
                        for (int k = 0; k < 32; k++) s = fmaf(s_ow2[j * 32 + k], h2[k], s);
                        o[j] = s;
                    }
                    *(float4*)(outp + ((size_t)b * TT + t) * 4) =
                        make_float4(o[0], o[1], o[2], o[3]);
                }
            }
        }
    }
}

// ---------------------------------------------------------------------------
extern "C" void kernel_launch(void* const* d_in, const int* in_sizes, int n_in,
                              void* d_out, int out_size)
{
    const float* x     = (const float*)d_in[0];
    const float* w1    = (const float*)d_in[1];
    const float* b1    = (const float*)d_in[2];
    const float* w2    = (const float*)d_in[3];
    const float* b2    = (const float*)d_in[4];
    const float* w_ih0 = (const float*)d_in[5];
    const float* w_hh0 = (const float*)d_in[6];
    const float* b_ih0 = (const float*)d_in[7];
    const float* b_hh0 = (const float*)d_in[8];
    const float* w_ih  = (const float*)d_in[9];   // (7, 256, 64)
    const float* w_hh  = (const float*)d_in[10];  // (7, 256, 64)
    const float* b_ih  = (const float*)d_in[11];  // (7, 256)
    const float* b_hh  = (const float*)d_in[12];  // (7, 256)
    const float* wo1   = (const float*)d_in[13];
    const float* bo1   = (const float*)d_in[14];
    const float* wo2   = (const float*)d_in[15];
    const float* bo2   = (const float*)d_in[16];
    float* outp = (float*)d_out;

    const int smem_sz = (20 * BT * 64 + 320 + 2048 + 32 + 128 + 4) * 4;  // 81808 B
    cudaFuncSetAttribute(model_kernel, cudaFuncAttributeMaxDynamicSharedMemorySize, smem_sz);

    model_kernel<<<NCTA, 512, smem_sz>>>(x, w1, b1, w2, b2,
                                         w_ih0, w_hh0, b_ih0, b_hh0,
                                         w_ih, w_hh, b_ih, b_hh,
                                         wo1, bo1, wo2, bo2, outp);
}